// round 13
// baseline (speedup 1.0000x reference)
#include <cuda_runtime.h>
#include <cuda_fp16.h>
#include <math.h>

#define N_NODES 100000
#define N_EDGES 1600000
#define D_IN 64
#define D_OUT 64
#define D_EDGE 16
#define NBLK_SCAN ((N_NODES + 255) / 256)   // 391
#define PRC_NODE_BLOCKS 12500               // 8 nodes/block (warp-per-node)
#define PRC_CNT_BLOCKS 6250                 // 256 edges/block
#define PRC_BLOCKS (PRC_NODE_BLOCKS + PRC_CNT_BLOCKS)

#define FMA_F32X2(d, a, b, c) \
    asm("fma.rn.f32x2 %0, %1, %2, %3;" : "=l"(d) : "l"(a), "l"(b), "l"(c))

// ---------------- scratch (device globals; no allocation) ----------------
__device__ float g_u[80];                         // W1^T @ att_l
__device__ float g_al[N_NODES];                   // x . u[0:64]
__device__ float g_ar[N_NODES];                   // x . att_r
__device__ __half2 g_xh[N_NODES * 32];            // x rows in half2 (lane l -> dims 2l,2l+1)
__device__ int   g_cnt[N_NODES];                  // in-degree; ZERO at rest (k_agg re-zeroes)
__device__ int   g_off[N_NODES];                  // CSR offsets (materialized)
__device__ int   g_rank[N_EDGES];                 // edge's arrival order within its dst
__device__ int   g_bsum[NBLK_SCAN];               // per-scan-block sums
__device__ unsigned long long g_cedge[N_EDGES];   // packed (ex<<32 | src)

// ---------------- K0: u[c] = sum_o att_l[o] * W1[o][c]  (computed ONCE) ----------------
__global__ void k_u(const float* __restrict__ W1, const float* __restrict__ att_l) {
    int c = threadIdx.x;
    if (c < 80) {
        float acc = 0.0f;
        #pragma unroll
        for (int o = 0; o < D_OUT; o++) acc += att_l[o] * W1[o * 80 + c];
        g_u[c] = acc;
    }
}

// ---------------- K1: FUSED split-grid: node pre-pass  ||  dst histogram ----------------
// blocks [0, PRC_NODE_BLOCKS): warp-per-node al/ar + half2 conversion
// blocks [PRC_NODE_BLOCKS, PRC_BLOCKS): per-edge rank via atomic histogram
// (g_cnt is guaranteed zero on entry: zero-init at load, re-zeroed by k_agg each run)
__global__ void k_prc(const float* __restrict__ x, const float* __restrict__ att_r,
                      const int* __restrict__ dst) {
    int tid = threadIdx.x;
    if (blockIdx.x < PRC_NODE_BLOCKS) {
        int n = (blockIdx.x * 256 + tid) >> 5;
        if (n >= N_NODES) return;
        int lane = tid & 31;

        float2 v = __ldg(reinterpret_cast<const float2*>(x) + n * 32 + lane);
        g_xh[n * 32 + lane] = __floats2half2_rn(v.x, v.y);

        float pa = v.x * g_u[2 * lane] + v.y * g_u[2 * lane + 1];
        float pr = v.x * __ldg(&att_r[2 * lane]) + v.y * __ldg(&att_r[2 * lane + 1]);
        #pragma unroll
        for (int off = 16; off; off >>= 1) {
            pa += __shfl_xor_sync(0xFFFFFFFFu, pa, off);
            pr += __shfl_xor_sync(0xFFFFFFFFu, pr, off);
        }
        if (lane == 0) {
            g_al[n] = pa;
            g_ar[n] = pr;
        }
    } else {
        int e = (blockIdx.x - PRC_NODE_BLOCKS) * 256 + tid;
        if (e < N_EDGES) g_rank[e] = atomicAdd(&g_cnt[dst[e]], 1);
    }
}

// ---------------- K2a: per-block exclusive scan (block-local) ----------------
__global__ void k_scan_a() {
    int tid = threadIdx.x, lane = tid & 31, wid = tid >> 5;
    int i = blockIdx.x * 256 + tid;
    int v = (i < N_NODES) ? g_cnt[i] : 0;
    int inc = v;
    #pragma unroll
    for (int d = 1; d < 32; d <<= 1) {
        int t = __shfl_up_sync(0xFFFFFFFFu, inc, d);
        if (lane >= d) inc += t;
    }
    __shared__ int wsum[8];
    if (lane == 31) wsum[wid] = inc;
    __syncthreads();
    if (tid < 8) {
        int w = wsum[tid];
        #pragma unroll
        for (int d = 1; d < 8; d <<= 1) {
            int t = __shfl_up_sync(0xFFu, w, d);
            if (tid >= d) w += t;
        }
        wsum[tid] = w;
    }
    __syncthreads();
    int base = (wid > 0) ? wsum[wid - 1] : 0;
    if (i < N_NODES) g_off[i] = base + inc - v;
    if (tid == 0) g_bsum[blockIdx.x] = wsum[7];
}

// ---------------- K2b: add cross-block base (each block reduces bsum[0..b)) ----------------
__global__ void k_scan_c() {
    int tid = threadIdx.x;
    int b = blockIdx.x;
    int acc = 0;
    for (int k = tid; k < b; k += 256) acc += g_bsum[k];
    #pragma unroll
    for (int off = 16; off; off >>= 1) acc += __shfl_xor_sync(0xFFFFFFFFu, acc, off);
    __shared__ int ws[8];
    if ((tid & 31) == 0) ws[tid >> 5] = acc;
    __syncthreads();
    __shared__ int base_s;
    if (tid == 0) {
        int t = 0;
        #pragma unroll
        for (int w = 0; w < 8; w++) t += ws[w];
        base_s = t;
    }
    __syncthreads();
    int i = b * 256 + tid;
    if (i < N_NODES) g_off[i] += base_s;
}

// ---------------- K3: fused edge score + atomic-free CSR scatter ----------------
__global__ void k_edge(const float* __restrict__ edge_attr,
                       const int* __restrict__ src, const int* __restrict__ dst) {
    __shared__ float su[16];
    if (threadIdx.x < 16) su[threadIdx.x] = g_u[64 + threadIdx.x];
    __syncthreads();

    int e = blockIdx.x * blockDim.x + threadIdx.x;
    if (e >= N_EDGES) return;

    const float4* ea = reinterpret_cast<const float4*>(edge_attr) + e * 4;
    float p = 0.0f;
    #pragma unroll
    for (int q = 0; q < 4; q++) {
        float4 v = __ldg(&ea[q]);
        p += v.x * su[q * 4 + 0] + v.y * su[q * 4 + 1]
           + v.z * su[q * 4 + 2] + v.w * su[q * 4 + 3];
    }
    int s = src[e], d = dst[e];
    float ee = g_al[s] + g_ar[d] + p;
    ee = (ee > 0.0f) ? ee : 0.01f * ee;
    float ex = __expf(ee);

    int pos = g_off[d] + g_rank[e];
    g_cedge[pos] =
        ((unsigned long long)__float_as_uint(ex) << 32) | (unsigned)s;
}

// ---------------- K4: PERSISTENT fused warp-per-dst aggregate + f32x2 GEMM
//                     + bias + LN  (R9-proven epilogue; g_cnt reset added) ----------------
#define AGG_BLOCKS 592
#define AGG_WARPS 16
__global__ void __launch_bounds__(512) k_agg(
        const float* __restrict__ W2, const float* __restrict__ bias,
        const float* __restrict__ gamma, const float* __restrict__ beta,
        float* __restrict__ out) {
    __shared__ __align__(16) float2 w2p[64 * 32];   // w2p[k*32+l] = (W2[2l][k], W2[2l+1][k])
    __shared__ __align__(16) float w2lin[4096];     // raw W2, coalesced staging
    __shared__ __align__(16) float2 a_sh[AGG_WARPS * 32];
    int tid = threadIdx.x;

    for (int i = tid; i < 4096; i += 512) w2lin[i] = W2[i];   // coalesced
    __syncthreads();
    for (int i = tid; i < 2048; i += 512) {
        int k = i >> 5, l = i & 31;
        w2p[i] = make_float2(w2lin[(2 * l) * 64 + k], w2lin[(2 * l + 1) * 64 + k]);
    }
    __syncthreads();

    int lane = tid & 31, wid = tid >> 5;

    for (int n = blockIdx.x * AGG_WARPS + wid; n < N_NODES;
         n += AGG_BLOCKS * AGG_WARPS) {
        int start = g_off[n];
        int cnt = g_cnt[n];
        if (lane == 0) g_cnt[n] = 0;      // reset: k_prc's histogram starts from zero next run
        const unsigned long long* ce = g_cedge + start;

        float ax = 0.0f, ay = 0.0f, den = 0.0f;  // lane -> dims (2*lane, 2*lane+1)

        int i = 0;
        for (; i + 4 <= cnt; i += 4) {
            unsigned long long q0 = ce[i + 0];
            unsigned long long q1 = ce[i + 1];
            unsigned long long q2 = ce[i + 2];
            unsigned long long q3 = ce[i + 3];
            int s0 = (int)(q0 & 0xFFFFFFFFu), s1 = (int)(q1 & 0xFFFFFFFFu);
            int s2 = (int)(q2 & 0xFFFFFFFFu), s3 = (int)(q3 & 0xFFFFFFFFu);
            float e0 = __uint_as_float((unsigned)(q0 >> 32));
            float e1 = __uint_as_float((unsigned)(q1 >> 32));
            float e2 = __uint_as_float((unsigned)(q2 >> 32));
            float e3 = __uint_as_float((unsigned)(q3 >> 32));
            float2 v0 = __half22float2(__ldg(&g_xh[s0 * 32 + lane]));
            float2 v1 = __half22float2(__ldg(&g_xh[s1 * 32 + lane]));
            float2 v2 = __half22float2(__ldg(&g_xh[s2 * 32 + lane]));
            float2 v3 = __half22float2(__ldg(&g_xh[s3 * 32 + lane]));
            den += (e0 + e1) + (e2 + e3);
            ax += e0 * v0.x + e1 * v1.x + e2 * v2.x + e3 * v3.x;
            ay += e0 * v0.y + e1 * v1.y + e2 * v2.y + e3 * v3.y;
        }
        for (; i < cnt; i++) {
            unsigned long long q0 = ce[i];
            int s0 = (int)(q0 & 0xFFFFFFFFu);
            float e0 = __uint_as_float((unsigned)(q0 >> 32));
            float2 v0 = __half22float2(__ldg(&g_xh[s0 * 32 + lane]));
            den += e0;
            ax += e0 * v0.x;
            ay += e0 * v0.y;
        }

        // stage A through smem; GEMM with zero shuffles (R9-proven form)
        a_sh[wid * 32 + lane] = make_float2(ax, ay);
        __syncwarp();

        unsigned long long acc = 0ull;
        const float2* arow = a_sh + wid * 32;
        #pragma unroll
        for (int q = 0; q < 32; q++) {
            float2 ap = arow[q];                  // LDS.64 broadcast
            unsigned long long a0, a1;
            asm("mov.b64 %0, {%1, %1};" : "=l"(a0) : "f"(ap.x));
            asm("mov.b64 %0, {%1, %1};" : "=l"(a1) : "f"(ap.y));
            unsigned long long w0 =
                *reinterpret_cast<const unsigned long long*>(&w2p[(2 * q) * 32 + lane]);
            unsigned long long w1 =
                *reinterpret_cast<const unsigned long long*>(&w2p[(2 * q + 1) * 32 + lane]);
            FMA_F32X2(acc, a0, w0, acc);
            FMA_F32X2(acc, a1, w1, acc);
        }
        __syncwarp();

        float h0, h1;
        asm("mov.b64 {%0, %1}, %2;" : "=f"(h0), "=f"(h1) : "l"(acc));

        float inv = (den > 0.0f) ? (1.0f / den) : 0.0f;
        float2 bv = __ldg(reinterpret_cast<const float2*>(bias) + lane);
        h0 = h0 * inv + bv.x;
        h1 = h1 * inv + bv.y;

        float sm = h0 + h1;
        #pragma unroll
        for (int off = 16; off; off >>= 1) sm += __shfl_xor_sync(0xFFFFFFFFu, sm, off);
        float mu = sm * (1.0f / 64.0f);

        float d0 = h0 - mu, d1 = h1 - mu;
        float vs = d0 * d0 + d1 * d1;
        #pragma unroll
        for (int off = 16; off; off >>= 1) vs += __shfl_xor_sync(0xFFFFFFFFu, vs, off);
        float rstd = rsqrtf(vs * (1.0f / 64.0f) + 1e-5f);

        float2 gv = __ldg(reinterpret_cast<const float2*>(gamma) + lane);
        float2 be = __ldg(reinterpret_cast<const float2*>(beta) + lane);
        reinterpret_cast<float2*>(out)[n * 32 + lane] =
            make_float2(d0 * rstd * gv.x + be.x, d1 * rstd * gv.y + be.y);
    }
}

// ---------------- launch ----------------
extern "C" void kernel_launch(void* const* d_in, const int* in_sizes, int n_in,
                              void* d_out, int out_size) {
    const float* x         = (const float*)d_in[0];
    const float* edge_attr = (const float*)d_in[1];
    const float* W1        = (const float*)d_in[2];
    const float* W2        = (const float*)d_in[3];
    const float* att_l     = (const float*)d_in[4];
    const float* att_r     = (const float*)d_in[5];
    const float* bias      = (const float*)d_in[6];
    const float* ln_gamma  = (const float*)d_in[7];
    const float* ln_beta   = (const float*)d_in[8];
    const int*   src       = (const int*)d_in[9];
    const int*   dst       = (const int*)d_in[10];
    float* out = (float*)d_out;

    k_u<<<1, 96>>>(W1, att_l);
    k_prc<<<PRC_BLOCKS, 256>>>(x, att_r, dst);     // node pre-pass || edge histogram
    k_scan_a<<<NBLK_SCAN, 256>>>();
    k_scan_c<<<NBLK_SCAN, 256>>>();
    k_edge<<<(N_EDGES + 255) / 256, 256>>>(edge_attr, src, dst);
    k_agg<<<AGG_BLOCKS, 512>>>(W2, bias, ln_gamma, ln_beta, out);
}

// round 14
// speedup vs baseline: 1.7671x; 1.7671x over previous
#include <cuda_runtime.h>
#include <cuda_fp16.h>
#include <math.h>

#define N_NODES 100000
#define N_EDGES 1600000
#define D_IN 64
#define D_OUT 64
#define D_EDGE 16
#define NBLK_SCAN ((N_NODES + 255) / 256)   // 391

#define FMA_F32X2(d, a, b, c) \
    asm("fma.rn.f32x2 %0, %1, %2, %3;" : "=l"(d) : "l"(a), "l"(b), "l"(c))

// ---------------- scratch (device globals; no allocation) ----------------
__device__ float g_u[80];                         // W1^T @ att_l
__device__ float g_al[N_NODES];                   // x . u[0:64]
__device__ float g_ar[N_NODES];                   // x . att_r
__device__ __half2 g_xh[N_NODES * 32];            // x rows in half2 (lane l -> dims 2l,2l+1)
__device__ int   g_cnt[N_NODES];
__device__ int   g_off[N_NODES];                  // CSR offsets (materialized)
__device__ int   g_rank[N_EDGES];                 // edge's arrival order within its dst
__device__ int   g_bsum[NBLK_SCAN];               // per-scan-block sums
__device__ unsigned long long g_cedge[N_EDGES];   // packed (ex<<32 | src)

// ---------------- K0: u[c] = sum_o att_l[o] * W1[o][c]  (computed ONCE) ----------------
__global__ void k_u(const float* __restrict__ W1, const float* __restrict__ att_l) {
    int c = threadIdx.x;
    if (c < 80) {
        float acc = 0.0f;
        #pragma unroll
        for (int o = 0; o < D_OUT; o++) acc += att_l[o] * W1[o * 80 + c];
        g_u[c] = acc;
    }
}

// ---------------- K1: warp-per-node al/ar + half2 conversion + zero cnt ----------------
__global__ void k_pre(const float* __restrict__ x, const float* __restrict__ att_r) {
    int n = (blockIdx.x * blockDim.x + threadIdx.x) >> 5;
    if (n >= N_NODES) return;
    int lane = threadIdx.x & 31;

    float2 v = __ldg(reinterpret_cast<const float2*>(x) + n * 32 + lane);
    g_xh[n * 32 + lane] = __floats2half2_rn(v.x, v.y);

    float pa = v.x * g_u[2 * lane] + v.y * g_u[2 * lane + 1];
    float pr = v.x * __ldg(&att_r[2 * lane]) + v.y * __ldg(&att_r[2 * lane + 1]);
    #pragma unroll
    for (int off = 16; off; off >>= 1) {
        pa += __shfl_xor_sync(0xFFFFFFFFu, pa, off);
        pr += __shfl_xor_sync(0xFFFFFFFFu, pr, off);
    }
    if (lane == 0) {
        g_al[n] = pa;
        g_ar[n] = pr;
        g_cnt[n] = 0;
    }
}

// ---------------- K2: histogram of dst + per-edge rank ----------------
__global__ void k_count(const int* __restrict__ dst) {
    int e = blockIdx.x * blockDim.x + threadIdx.x;
    if (e < N_EDGES) g_rank[e] = atomicAdd(&g_cnt[dst[e]], 1);
}

// ---------------- K3a: per-block exclusive scan (block-local) ----------------
__global__ void k_scan_a() {
    int tid = threadIdx.x, lane = tid & 31, wid = tid >> 5;
    int i = blockIdx.x * 256 + tid;
    int v = (i < N_NODES) ? g_cnt[i] : 0;
    int inc = v;
    #pragma unroll
    for (int d = 1; d < 32; d <<= 1) {
        int t = __shfl_up_sync(0xFFFFFFFFu, inc, d);
        if (lane >= d) inc += t;
    }
    __shared__ int wsum[8];
    if (lane == 31) wsum[wid] = inc;
    __syncthreads();
    if (tid < 8) {
        int w = wsum[tid];
        #pragma unroll
        for (int d = 1; d < 8; d <<= 1) {
            int t = __shfl_up_sync(0xFFu, w, d);
            if (tid >= d) w += t;
        }
        wsum[tid] = w;
    }
    __syncthreads();
    int base = (wid > 0) ? wsum[wid - 1] : 0;
    if (i < N_NODES) g_off[i] = base + inc - v;
    if (tid == 0) g_bsum[blockIdx.x] = wsum[7];
}

// ---------------- K3b: add cross-block base (each block reduces bsum[0..b)) ----------------
__global__ void k_scan_c() {
    int tid = threadIdx.x;
    int b = blockIdx.x;
    int acc = 0;
    for (int k = tid; k < b; k += 256) acc += g_bsum[k];
    #pragma unroll
    for (int off = 16; off; off >>= 1) acc += __shfl_xor_sync(0xFFFFFFFFu, acc, off);
    __shared__ int ws[8];
    if ((tid & 31) == 0) ws[tid >> 5] = acc;
    __syncthreads();
    __shared__ int base_s;
    if (tid == 0) {
        int t = 0;
        #pragma unroll
        for (int w = 0; w < 8; w++) t += ws[w];
        base_s = t;
    }
    __syncthreads();
    int i = b * 256 + tid;
    if (i < N_NODES) g_off[i] += base_s;
}

// ---------------- K4: fused edge score + atomic-free CSR scatter ----------------
__global__ void k_edge(const float* __restrict__ edge_attr,
                       const int* __restrict__ src, const int* __restrict__ dst) {
    __shared__ float su[16];
    if (threadIdx.x < 16) su[threadIdx.x] = g_u[64 + threadIdx.x];
    __syncthreads();

    int e = blockIdx.x * blockDim.x + threadIdx.x;
    if (e >= N_EDGES) return;

    const float4* ea = reinterpret_cast<const float4*>(edge_attr) + e * 4;
    float p = 0.0f;
    #pragma unroll
    for (int q = 0; q < 4; q++) {
        float4 v = __ldg(&ea[q]);
        p += v.x * su[q * 4 + 0] + v.y * su[q * 4 + 1]
           + v.z * su[q * 4 + 2] + v.w * su[q * 4 + 3];
    }
    int s = src[e], d = dst[e];
    float ee = g_al[s] + g_ar[d] + p;
    ee = (ee > 0.0f) ? ee : 0.01f * ee;
    float ex = __expf(ee);

    int pos = g_off[d] + g_rank[e];
    g_cedge[pos] =
        ((unsigned long long)__float_as_uint(ex) << 32) | (unsigned)s;
}

// ---------------- K5: PERSISTENT fused warp-per-dst aggregate + f32x2 GEMM
//                     + bias + LN.  Grid sized to EXACT residency at launch. ----------------
#define AGG_WARPS 16
__global__ void __launch_bounds__(512) k_agg(
        const float* __restrict__ W2, const float* __restrict__ bias,
        const float* __restrict__ gamma, const float* __restrict__ beta,
        float* __restrict__ out) {
    __shared__ __align__(16) float2 w2p[64 * 32];   // w2p[k*32+l] = (W2[2l][k], W2[2l+1][k])
    __shared__ __align__(16) float w2lin[4096];     // raw W2, coalesced staging
    __shared__ __align__(16) float2 a_sh[AGG_WARPS * 32];
    int tid = threadIdx.x;

    for (int i = tid; i < 4096; i += 512) w2lin[i] = W2[i];   // coalesced
    __syncthreads();
    for (int i = tid; i < 2048; i += 512) {
        int k = i >> 5, l = i & 31;
        w2p[i] = make_float2(w2lin[(2 * l) * 64 + k], w2lin[(2 * l + 1) * 64 + k]);
    }
    __syncthreads();

    int lane = tid & 31, wid = tid >> 5;
    int stride = gridDim.x * AGG_WARPS;

    for (int n = blockIdx.x * AGG_WARPS + wid; n < N_NODES; n += stride) {
        int start = g_off[n];
        int cnt = g_cnt[n];
        const unsigned long long* ce = g_cedge + start;

        float ax = 0.0f, ay = 0.0f, den = 0.0f;  // lane -> dims (2*lane, 2*lane+1)

        int i = 0;
        for (; i + 4 <= cnt; i += 4) {
            unsigned long long q0 = ce[i + 0];
            unsigned long long q1 = ce[i + 1];
            unsigned long long q2 = ce[i + 2];
            unsigned long long q3 = ce[i + 3];
            int s0 = (int)(q0 & 0xFFFFFFFFu), s1 = (int)(q1 & 0xFFFFFFFFu);
            int s2 = (int)(q2 & 0xFFFFFFFFu), s3 = (int)(q3 & 0xFFFFFFFFu);
            float e0 = __uint_as_float((unsigned)(q0 >> 32));
            float e1 = __uint_as_float((unsigned)(q1 >> 32));
            float e2 = __uint_as_float((unsigned)(q2 >> 32));
            float e3 = __uint_as_float((unsigned)(q3 >> 32));
            float2 v0 = __half22float2(__ldg(&g_xh[s0 * 32 + lane]));
            float2 v1 = __half22float2(__ldg(&g_xh[s1 * 32 + lane]));
            float2 v2 = __half22float2(__ldg(&g_xh[s2 * 32 + lane]));
            float2 v3 = __half22float2(__ldg(&g_xh[s3 * 32 + lane]));
            den += (e0 + e1) + (e2 + e3);
            ax += e0 * v0.x + e1 * v1.x + e2 * v2.x + e3 * v3.x;
            ay += e0 * v0.y + e1 * v1.y + e2 * v2.y + e3 * v3.y;
        }
        for (; i < cnt; i++) {
            unsigned long long q0 = ce[i];
            int s0 = (int)(q0 & 0xFFFFFFFFu);
            float e0 = __uint_as_float((unsigned)(q0 >> 32));
            float2 v0 = __half22float2(__ldg(&g_xh[s0 * 32 + lane]));
            den += e0;
            ax += e0 * v0.x;
            ay += e0 * v0.y;
        }

        // stage A through smem; GEMM with zero shuffles (R9-proven form)
        a_sh[wid * 32 + lane] = make_float2(ax, ay);
        __syncwarp();

        unsigned long long acc = 0ull;
        const float2* arow = a_sh + wid * 32;
        #pragma unroll
        for (int q = 0; q < 32; q++) {
            float2 ap = arow[q];                  // LDS.64 broadcast
            unsigned long long a0, a1;
            asm("mov.b64 %0, {%1, %1};" : "=l"(a0) : "f"(ap.x));
            asm("mov.b64 %0, {%1, %1};" : "=l"(a1) : "f"(ap.y));
            unsigned long long w0 =
                *reinterpret_cast<const unsigned long long*>(&w2p[(2 * q) * 32 + lane]);
            unsigned long long w1 =
                *reinterpret_cast<const unsigned long long*>(&w2p[(2 * q + 1) * 32 + lane]);
            FMA_F32X2(acc, a0, w0, acc);
            FMA_F32X2(acc, a1, w1, acc);
        }
        __syncwarp();

        float h0, h1;
        asm("mov.b64 {%0, %1}, %2;" : "=f"(h0), "=f"(h1) : "l"(acc));

        float inv = (den > 0.0f) ? (1.0f / den) : 0.0f;
        float2 bv = __ldg(reinterpret_cast<const float2*>(bias) + lane);
        h0 = h0 * inv + bv.x;
        h1 = h1 * inv + bv.y;

        float sm = h0 + h1;
        #pragma unroll
        for (int off = 16; off; off >>= 1) sm += __shfl_xor_sync(0xFFFFFFFFu, sm, off);
        float mu = sm * (1.0f / 64.0f);

        float d0 = h0 - mu, d1 = h1 - mu;
        float vs = d0 * d0 + d1 * d1;
        #pragma unroll
        for (int off = 16; off; off >>= 1) vs += __shfl_xor_sync(0xFFFFFFFFu, vs, off);
        float rstd = rsqrtf(vs * (1.0f / 64.0f) + 1e-5f);

        float2 gv = __ldg(reinterpret_cast<const float2*>(gamma) + lane);
        float2 be = __ldg(reinterpret_cast<const float2*>(beta) + lane);
        reinterpret_cast<float2*>(out)[n * 32 + lane] =
            make_float2(d0 * rstd * gv.x + be.x, d1 * rstd * gv.y + be.y);
    }
}

// ---------------- launch ----------------
extern "C" void kernel_launch(void* const* d_in, const int* in_sizes, int n_in,
                              void* d_out, int out_size) {
    const float* x         = (const float*)d_in[0];
    const float* edge_attr = (const float*)d_in[1];
    const float* W1        = (const float*)d_in[2];
    const float* W2        = (const float*)d_in[3];
    const float* att_l     = (const float*)d_in[4];
    const float* att_r     = (const float*)d_in[5];
    const float* bias      = (const float*)d_in[6];
    const float* ln_gamma  = (const float*)d_in[7];
    const float* ln_beta   = (const float*)d_in[8];
    const int*   src       = (const int*)d_in[9];
    const int*   dst       = (const int*)d_in[10];
    float* out = (float*)d_out;

    // exact-residency persistent grid for k_agg: one clean wave, no
    // persistent-block serialization (deterministic: same device, same value).
    int bpm = 0, nsm = 0, dev = 0;
    cudaGetDevice(&dev);
    cudaOccupancyMaxActiveBlocksPerMultiprocessor(&bpm, k_agg, 512, 0);
    cudaDeviceGetAttribute(&nsm, cudaDevAttrMultiProcessorCount, dev);
    int agg_blocks = (bpm > 0 && nsm > 0) ? bpm * nsm : 444;

    k_u<<<1, 96>>>(W1, att_l);
    k_pre<<<(N_NODES * 32 + 255) / 256, 256>>>(x, att_r);
    k_count<<<(N_EDGES + 255) / 256, 256>>>(dst);
    k_scan_a<<<NBLK_SCAN, 256>>>();
    k_scan_c<<<NBLK_SCAN, 256>>>();
    k_edge<<<(N_EDGES + 255) / 256, 256>>>(edge_attr, src, dst);
    k_agg<<<agg_blocks, 512>>>(W2, bias, ln_gamma, ln_beta, out);
}